// round 1
// baseline (speedup 1.0000x reference)
#include <cuda_runtime.h>
#include <cuda_bf16.h>

// GCN 2-layer:
//   layer1: agg over edges of x[src]*coef (5-dim!) then GEMM 5x128 + relu
//   layer2: per-node scalar s = h . W2, then agg scalars over edges
// coef = dinv[src]*dinv[dst],  dinv = rsqrt(dst_degree + 1)

#define MAXN 131072
#define IN_DIM 5
#define HID 128

__device__ float g_deg[MAXN];
__device__ float g_dinv[MAXN];
__device__ float g_z[MAXN * IN_DIM];
__device__ float g_s[MAXN];

__global__ void k_zero(int n) {
    int i = blockIdx.x * blockDim.x + threadIdx.x;
    if (i >= n) return;
    g_deg[i] = 0.0f;
#pragma unroll
    for (int j = 0; j < IN_DIM; j++) g_z[i * IN_DIM + j] = 0.0f;
}

__global__ void k_degree(const int* __restrict__ dst, int E) {
    int e = blockIdx.x * blockDim.x + threadIdx.x;
    if (e >= E) return;
    atomicAdd(&g_deg[dst[e]], 1.0f);
}

__global__ void k_dinv(int n) {
    int i = blockIdx.x * blockDim.x + threadIdx.x;
    if (i >= n) return;
    g_dinv[i] = 1.0f / sqrtf(g_deg[i] + 1.0f);
}

// Edge aggregation of raw 5-dim features: z[dst] += x[src] * coef
__global__ void k_edge_agg1(const int* __restrict__ src, const int* __restrict__ dst,
                            const float* __restrict__ x, int E) {
    int e = blockIdx.x * blockDim.x + threadIdx.x;
    if (e >= E) return;
    int s = src[e];
    int d = dst[e];
    float c = g_dinv[s] * g_dinv[d];
#pragma unroll
    for (int j = 0; j < IN_DIM; j++) {
        atomicAdd(&g_z[d * IN_DIM + j], x[s * IN_DIM + j] * c);
    }
}

// Per-node: z_total = z + x*dinv^2 ; h = relu(z_total @ W1 + b1) ; s = h . W2
// Also writes the layer-2 self-loop contribution into out.
__global__ void k_node(const float* __restrict__ x,
                       const float* __restrict__ W1, const float* __restrict__ b1,
                       const float* __restrict__ W2, const float* __restrict__ b2,
                       float* __restrict__ out, int n) {
    __shared__ float sW1[IN_DIM * HID];
    __shared__ float sb1[HID];
    __shared__ float sW2[HID];
    for (int i = threadIdx.x; i < IN_DIM * HID; i += blockDim.x) sW1[i] = W1[i];
    if (threadIdx.x < HID) {
        sb1[threadIdx.x] = b1[threadIdx.x];
        sW2[threadIdx.x] = W2[threadIdx.x];
    }
    __syncthreads();

    int i = blockIdx.x * blockDim.x + threadIdx.x;
    if (i >= n) return;

    float di = g_dinv[i];
    float d2 = di * di;
    float zj[IN_DIM];
#pragma unroll
    for (int j = 0; j < IN_DIM; j++) {
        zj[j] = g_z[i * IN_DIM + j] + x[i * IN_DIM + j] * d2;
    }

    float s = 0.0f;
#pragma unroll 4
    for (int k = 0; k < HID; k++) {
        float acc = sb1[k];
#pragma unroll
        for (int j = 0; j < IN_DIM; j++) acc = fmaf(zj[j], sW1[j * HID + k], acc);
        acc = fmaxf(acc, 0.0f);
        s = fmaf(acc, sW2[k], s);
    }
    g_s[i] = s;
    out[i] = s * d2 + b2[0];   // layer-2 self-loop + bias
}

// Edge aggregation of scalar s: out[dst] += s[src] * coef
__global__ void k_edge_agg2(const int* __restrict__ src, const int* __restrict__ dst,
                            float* __restrict__ out, int E) {
    int e = blockIdx.x * blockDim.x + threadIdx.x;
    if (e >= E) return;
    int s = src[e];
    int d = dst[e];
    atomicAdd(&out[d], g_s[s] * g_dinv[s] * g_dinv[d]);
}

extern "C" void kernel_launch(void* const* d_in, const int* in_sizes, int n_in,
                              void* d_out, int out_size) {
    const float* x  = (const float*)d_in[0];
    const int* ei   = (const int*)d_in[1];   // [2, E] row-major: src first, dst second
    const float* W1 = (const float*)d_in[2];
    const float* b1 = (const float*)d_in[3];
    const float* W2 = (const float*)d_in[4];
    const float* b2 = (const float*)d_in[5];
    float* out = (float*)d_out;

    int n = in_sizes[0] / IN_DIM;
    int E = in_sizes[1] / 2;
    const int* src = ei;
    const int* dst = ei + E;

    const int TB = 256;
    int gb_n = (n + TB - 1) / TB;
    int gb_e = (E + TB - 1) / TB;

    k_zero<<<gb_n, TB>>>(n);
    k_degree<<<gb_e, TB>>>(dst, E);
    k_dinv<<<gb_n, TB>>>(n);
    k_edge_agg1<<<gb_e, TB>>>(src, dst, x, E);
    k_node<<<gb_n, TB>>>(x, W1, b1, W2, b2, out, n);
    k_edge_agg2<<<gb_e, TB>>>(src, dst, out, E);
}

// round 2
// speedup vs baseline: 1.7233x; 1.7233x over previous
#include <cuda_runtime.h>
#include <cuda_bf16.h>

// GCN 2-layer, restructured so edge passes move minimal data:
//   y[i]   = x[i] * dinv[i]            (5 floats, padded to 8 = one 32B sector)
//   z[d]   = sum_edges y[src]          (red.v4 + red.f32 atomics)
//   zt[i]  = z[i]*dinv[i] + x[i]*dinv[i]^2
//   h      = relu(zt @ W1 + b1);  s = h . W2
//   t[i]   = s[i] * dinv[i]
//   acc[d] = sum_edges t[src]          (1 scalar red per edge)
//   out[i] = acc[i]*dinv[i] + s[i]*dinv[i]^2 + b2

#define MAXN 131072
#define IN_DIM 5
#define PAD 8
#define HID 128

__device__ float g_deg[MAXN];
__device__ float g_dinv[MAXN];
__device__ __align__(128) float g_y[MAXN * PAD];
__device__ __align__(128) float g_z[MAXN * PAD];
__device__ float g_s[MAXN];
__device__ float g_t[MAXN];
__device__ float g_acc[MAXN];

__device__ __forceinline__ void red_v4(float* p, float a, float b, float c, float d) {
    asm volatile("red.global.add.v4.f32 [%0], {%1, %2, %3, %4};"
                 :: "l"(p), "f"(a), "f"(b), "f"(c), "f"(d) : "memory");
}

__global__ void k_zero(int n) {
    int i = blockIdx.x * blockDim.x + threadIdx.x;
    if (i >= n) return;
    g_deg[i] = 0.0f;
    g_acc[i] = 0.0f;
    float4 z4 = make_float4(0.f, 0.f, 0.f, 0.f);
    *(float4*)&g_z[i * PAD] = z4;
    *(float4*)&g_z[i * PAD + 4] = z4;
}

__global__ void k_degree(const int* __restrict__ dst, int E) {
    int e = blockIdx.x * blockDim.x + threadIdx.x;
    if (e >= E) return;
    atomicAdd(&g_deg[dst[e]], 1.0f);
}

// dinv + padded scaled features y = x*dinv
__global__ void k_prep(const float* __restrict__ x, int n) {
    int i = blockIdx.x * blockDim.x + threadIdx.x;
    if (i >= n) return;
    float di = rsqrtf(g_deg[i] + 1.0f);
    g_dinv[i] = di;
    float y0 = x[i * IN_DIM + 0] * di;
    float y1 = x[i * IN_DIM + 1] * di;
    float y2 = x[i * IN_DIM + 2] * di;
    float y3 = x[i * IN_DIM + 3] * di;
    float y4 = x[i * IN_DIM + 4] * di;
    *(float4*)&g_y[i * PAD] = make_float4(y0, y1, y2, y3);
    *(float4*)&g_y[i * PAD + 4] = make_float4(y4, 0.f, 0.f, 0.f);
}

// Edge pass 1: z[dst] += y[src]   (2 red instrs, ~2 random L2 sectors/edge)
__global__ void k_edge_agg1(const int* __restrict__ src, const int* __restrict__ dst, int E) {
    int e = blockIdx.x * blockDim.x + threadIdx.x;
    if (e >= E) return;
    int s = src[e];
    int d = dst[e];
    float4 y4 = *(const float4*)&g_y[s * PAD];
    float y5 = g_y[s * PAD + 4];
    red_v4(&g_z[d * PAD], y4.x, y4.y, y4.z, y4.w);
    atomicAdd(&g_z[d * PAD + 4], y5);
}

// Per-node: zt = z*dinv + x*dinv^2 ; h = relu(zt@W1+b1) ; s = h.W2
// writes t = s*dinv and the self-loop part of out.
__global__ void k_node(const float* __restrict__ x,
                       const float* __restrict__ W1, const float* __restrict__ b1,
                       const float* __restrict__ W2, const float* __restrict__ b2,
                       float* __restrict__ out, int n) {
    __shared__ float sW1[IN_DIM * HID];
    __shared__ float sb1[HID];
    __shared__ float sW2[HID];
    for (int i = threadIdx.x; i < IN_DIM * HID; i += blockDim.x) sW1[i] = W1[i];
    if (threadIdx.x < HID) {
        sb1[threadIdx.x] = b1[threadIdx.x];
        sW2[threadIdx.x] = W2[threadIdx.x];
    }
    __syncthreads();

    int i = blockIdx.x * blockDim.x + threadIdx.x;
    if (i >= n) return;

    float di = g_dinv[i];
    float d2 = di * di;
    float zt[IN_DIM];
#pragma unroll
    for (int j = 0; j < IN_DIM; j++) {
        zt[j] = g_z[i * PAD + j] * di + x[i * IN_DIM + j] * d2;
    }

    float s = 0.0f;
#pragma unroll 4
    for (int k = 0; k < HID; k++) {
        float acc = sb1[k];
#pragma unroll
        for (int j = 0; j < IN_DIM; j++) acc = fmaf(zt[j], sW1[j * HID + k], acc);
        acc = fmaxf(acc, 0.0f);
        s = fmaf(acc, sW2[k], s);
    }
    g_s[i] = s;
    g_t[i] = s * di;
    out[i] = s * d2 + b2[0];
}

// Edge pass 2: acc[dst] += t[src]   (1 gather + 1 red per edge)
__global__ void k_edge_agg2(const int* __restrict__ src, const int* __restrict__ dst, int E) {
    int e = blockIdx.x * blockDim.x + threadIdx.x;
    if (e >= E) return;
    atomicAdd(&g_acc[dst[e]], g_t[src[e]]);
}

__global__ void k_final(float* __restrict__ out, int n) {
    int i = blockIdx.x * blockDim.x + threadIdx.x;
    if (i >= n) return;
    out[i] += g_acc[i] * g_dinv[i];
}

extern "C" void kernel_launch(void* const* d_in, const int* in_sizes, int n_in,
                              void* d_out, int out_size) {
    const float* x  = (const float*)d_in[0];
    const int* ei   = (const int*)d_in[1];   // [2, E]: src row then dst row
    const float* W1 = (const float*)d_in[2];
    const float* b1 = (const float*)d_in[3];
    const float* W2 = (const float*)d_in[4];
    const float* b2 = (const float*)d_in[5];
    float* out = (float*)d_out;

    int n = in_sizes[0] / IN_DIM;
    int E = in_sizes[1] / 2;
    const int* src = ei;
    const int* dst = ei + E;

    const int TB = 256;
    int gb_n = (n + TB - 1) / TB;
    int gb_e = (E + TB - 1) / TB;

    k_zero<<<gb_n, TB>>>(n);
    k_degree<<<gb_e, TB>>>(dst, E);
    k_prep<<<gb_n, TB>>>(x, n);
    k_edge_agg1<<<gb_e, TB>>>(src, dst, E);
    k_node<<<gb_n, TB>>>(x, W1, b1, W2, b2, out, n);
    k_edge_agg2<<<gb_e, TB>>>(src, dst, E);
    k_final<<<gb_n, TB>>>(out, n);
}